// round 13
// baseline (speedup 1.0000x reference)
#include <cuda_runtime.h>
#include <cuda_fp16.h>
#include <math.h>
#include <stdint.h>

#define NN      100000
#define EE      1600000
#define GG      512
#define INDIM   1024
#define HID     128
#define HEADS   4
#define LDP     40          // fp16 smem row pitch (80 B), ldmatrix conflict-free
#define GEMM_BLOCKS  296    // persistent: 2 CTAs/SM

// ================= static device scratch =================
__device__ float g_X[NN * HID];
__device__ float g_H[NN * HID];
__device__ float g_as[NN * HEADS];
__device__ float g_ad[NN * HEADS];
__device__ int   g_rowptr[NN + 1];
__device__ int   g_cursor[NN];      // zero at load; every replay re-zeroes in pool launch
__device__ int   g_colsrc[EE];
__device__ int   g_blocksum[128];
__device__ int   g_gstart[GG + 1];
__device__ __half g_W1T[HID * INDIM];    // [n][k] fp16
__device__ __half g_WgT[2 * HID * HID];  // fp16

// ================= fused init: hist + weight prep + gstart =================
#define INIT_GRID 7281
__global__ __launch_bounds__(256)
void init_kernel(const float* __restrict__ W1, const float* __restrict__ Wg,
                 const int* __restrict__ ei, const int* __restrict__ batch) {
    int b = blockIdx.x, t = threadIdx.x;
    if (b < 6250) {
        int e = b * 256 + t;
        if (e < EE) atomicAdd(&g_cursor[ei[EE + e]], 1);
    } else if (b < 6762) {
        int idx = (b - 6250) * 256 + t;
        int n = idx >> 10, k = idx & 1023;
        g_W1T[idx] = __float2half_rn(W1[k * HID + n]);
    } else if (b < 6890) {
        int idx = (b - 6762) * 256 + t;
        int l = idx >> 14, n = (idx >> 7) & 127, k = idx & 127;
        g_WgT[idx] = __float2half_rn(Wg[l * HID * HID + k * HID + n]);
    } else {
        int i = (b - 6890) * 256 + t;
        if (i >= NN) return;
        int bb = batch[i];
        int prev = (i == 0) ? -1 : batch[i - 1];
        for (int g = prev + 1; g <= bb; g++) g_gstart[g] = i;
        if (i == NN - 1)
            for (int g = bb + 1; g <= GG; g++) g_gstart[g] = NN;
    }
}

// ---- scan phase 1 ----
__global__ void scan_block_kernel() {        // grid 98, block 1024
    __shared__ int sm[1024];
    int b = blockIdx.x, t = threadIdx.x;
    int i = b * 1024 + t;
    int v = (i < NN) ? g_cursor[i] : 0;
    sm[t] = v;
    __syncthreads();
    #pragma unroll
    for (int off = 1; off < 1024; off <<= 1) {
        int add = (t >= off) ? sm[t - off] : 0;
        __syncthreads();
        sm[t] += add;
        __syncthreads();
    }
    if (i < NN) g_rowptr[i + 1] = sm[t];
    if (t == 1023) g_blocksum[b] = sm[1023];
}

// ---- scan phase 2 ----
__global__ void scan_add2_kernel(int nblocks) {   // grid 98, block 1024
    __shared__ int sm[128];
    int b = blockIdx.x, t = threadIdx.x;
    if (t < 128) sm[t] = (t < nblocks) ? g_blocksum[t] : 0;
    __syncthreads();
    #pragma unroll
    for (int off = 1; off < 128; off <<= 1) {
        int add = (t < 128 && t >= off) ? sm[t - off] : 0;
        __syncthreads();
        if (t < 128) sm[t] += add;
        __syncthreads();
    }
    int boff = (b == 0) ? 0 : sm[b - 1];
    int i = b * 1024 + t;
    if (i < NN) {
        int incl = g_rowptr[i + 1] + boff;
        g_rowptr[i + 1] = incl;
        g_cursor[i] = incl - g_cursor[i];
    }
    if (i == 0) g_rowptr[0] = 0;
}

// ================= mma helpers =================
__device__ __forceinline__ uint32_t smem_u32(const void* p) {
    uint32_t a;
    asm("{ .reg .u64 t; cvta.to.shared.u64 t, %1; cvt.u32.u64 %0, t; }" : "=r"(a) : "l"(p));
    return a;
}
__device__ __forceinline__ void ldmatrix_x4(uint32_t& r0, uint32_t& r1, uint32_t& r2, uint32_t& r3,
                                            uint32_t addr) {
    asm volatile("ldmatrix.sync.aligned.m8n8.x4.shared.b16 {%0,%1,%2,%3}, [%4];"
                 : "=r"(r0), "=r"(r1), "=r"(r2), "=r"(r3) : "r"(addr));
}
__device__ __forceinline__ void mma_f16(float* c, const uint32_t* a, const uint32_t* b) {
    asm volatile(
        "mma.sync.aligned.m16n8k16.row.col.f32.f16.f16.f32 "
        "{%0,%1,%2,%3}, {%4,%5,%6,%7}, {%8,%9}, {%0,%1,%2,%3};"
        : "+f"(c[0]), "+f"(c[1]), "+f"(c[2]), "+f"(c[3])
        : "r"(a[0]), "r"(a[1]), "r"(a[2]), "r"(a[3]), "r"(b[0]), "r"(b[1]));
}
__device__ __forceinline__ void cp_async16(uint32_t dst, const void* src) {
    asm volatile("cp.async.cg.shared.global [%0], [%1], 16;" :: "r"(dst), "l"(src));
}
#define CP_COMMIT() asm volatile("cp.async.commit_group;" ::: "memory")
#define CP_WAIT1()  asm volatile("cp.async.wait_group 1;" ::: "memory")

// ================= persistent 3-stage cp.async HMMA fp16 GEMM (2 CTAs/SM) =================
// smem layout (bytes):
//   A16 (single)   @ 0            10240   (128 x LDP fp16, ldmatrix layout)
//   A32 stage s    @ 10240 + s*16384     (128 x 32 fp32, linear, pitch 128 B)
//   B16 stage s    @ 59392 + s*10240     (128 x LDP fp16, ldmatrix layout)
#define OFF_A16  0
#define OFF_A32  10240
#define OFF_B16  59392
#define TCG_SMEM 90112

__global__ __launch_bounds__(256, 2)
void mma_gemm_kernel(const float* __restrict__ A,
                     const __half* __restrict__ BT,
                     const float* __restrict__ bias,
                     float* __restrict__ C,
                     int M, int K, int apply_gelu,
                     const float* __restrict__ asrc,   // [128] flat or null
                     const float* __restrict__ adst,
                     const int* __restrict__ ei_scat) { // post-loop scatter (GEMM1 only)
    extern __shared__ char dsm[];
    const int t = threadIdx.x;
    const int lane = t & 31, wid = t >> 5;
    const int wm = wid & 3;
    const int wn = wid >> 2;

    const int a_lrow = lane & 15;
    const int a_c8   = (lane >> 4) << 3;
    const int b_lrow = (lane & 7) + ((lane >> 4) << 3);
    const int b_c8   = ((lane >> 3) & 1) << 3;
    const int nchunks = K >> 5;
    const int ntiles = (M + 127) >> 7;

    const uint32_t uBase = smem_u32(dsm);
    const uint32_t uA16  = uBase + OFF_A16;

    // per-thread fixed offsets
    const int ld_r   = t >> 3;            // 0..31 (row group for A loads; 4 rows x 8 segs per 256)
    const int ld_seg = t & 7;             // 16B segment in a 128B row
    const int b_r    = t >> 2;            // B: 64 rows per 256 threads? -> idx mapping below

    for (int tile = blockIdx.x; tile < ntiles; tile += (int)gridDim.x) {
        const int row0 = tile << 7;

        float acc[2][8][4];
        #pragma unroll
        for (int i = 0; i < 2; i++)
            #pragma unroll
            for (int j = 0; j < 8; j++)
                #pragma unroll
                for (int q = 0; q < 4; q++) acc[i][j][q] = 0.0f;

        // ---- prologue: issue groups for chunks 0 and 1 ----
        #pragma unroll
        for (int pc = 0; pc < 2; pc++) {
            if (pc < nchunks) {
                const int k0 = pc << 5;
                char* a32 = dsm + OFF_A32 + pc * 16384;
                char* b16 = dsm + OFF_B16 + pc * 10240;
                #pragma unroll
                for (int j = 0; j < 4; j++) {
                    int idx = t + j * 256;               // 0..1023
                    int r = idx >> 3, seg = idx & 7;
                    int gr = row0 + r;
                    const float* src = &A[(size_t)(gr < M ? gr : M - 1) * K + k0 + seg * 4];
                    // rows >= M: still load valid address (row M-1); converted values
                    // for OOB rows produce garbage C rows that are never stored.
                    cp_async16(smem_u32(a32 + r * 128 + seg * 16), src);
                }
                #pragma unroll
                for (int j = 0; j < 2; j++) {
                    int idx = t + j * 256;               // 0..511
                    int r = idx >> 2, colv = (idx & 3) << 3;
                    cp_async16(smem_u32(b16 + (r * LDP + colv) * 2),
                               BT + (size_t)r * K + k0 + colv);
                }
            }
            CP_COMMIT();
        }

        for (int c = 0; c < nchunks; c++) {
            const int s = c % 3;
            CP_WAIT1();                                   // group c complete

            // ---- convert A32(s) -> A16 (each thread converts the bytes it copied) ----
            {
                char* a32 = dsm + OFF_A32 + s * 16384;
                __half* sA = (__half*)(dsm + OFF_A16);
                #pragma unroll
                for (int j = 0; j < 4; j++) {
                    int idx = t + j * 256;
                    int r = idx >> 3, seg = idx & 7;
                    float4 v = *(const float4*)(a32 + r * 128 + seg * 16);
                    uint2 hv;
                    asm("cvt.rn.f16x2.f32 %0, %1, %2;" : "=r"(hv.x) : "f"(v.y), "f"(v.x));
                    asm("cvt.rn.f16x2.f32 %0, %1, %2;" : "=r"(hv.y) : "f"(v.w), "f"(v.z));
                    *(uint2*)&sA[r * LDP + seg * 4] = hv;
                }
            }
            __syncthreads();   // A16 + B16(s) visible to all

            // ---- issue group c+2 ----
            {
                const int cn = c + 2;
                if (cn < nchunks) {
                    const int k0 = cn << 5;
                    const int sn = cn % 3;
                    char* a32 = dsm + OFF_A32 + sn * 16384;
                    char* b16 = dsm + OFF_B16 + sn * 10240;
                    #pragma unroll
                    for (int j = 0; j < 4; j++) {
                        int idx = t + j * 256;
                        int r = idx >> 3, seg = idx & 7;
                        int gr = row0 + r;
                        const float* src = &A[(size_t)(gr < M ? gr : M - 1) * K + k0 + seg * 4];
                        cp_async16(smem_u32(a32 + r * 128 + seg * 16), src);
                    }
                    #pragma unroll
                    for (int j = 0; j < 2; j++) {
                        int idx = t + j * 256;
                        int r = idx >> 2, colv = (idx & 3) << 3;
                        cp_async16(smem_u32(b16 + (r * LDP + colv) * 2),
                                   BT + (size_t)r * K + k0 + colv);
                    }
                }
                CP_COMMIT();
            }

            // ---- compute on A16 + B16(s) ----
            const uint32_t uB = uBase + OFF_B16 + s * 10240;
            #pragma unroll
            for (int ks = 0; ks < 2; ks++) {
                const int kc = ks * 16;
                uint32_t ah[2][4];
                #pragma unroll
                for (int mf = 0; mf < 2; mf++) {
                    uint32_t off = (uint32_t)((wm * 32 + mf * 16 + a_lrow) * 80 + (kc + a_c8) * 2);
                    ldmatrix_x4(ah[mf][0], ah[mf][1], ah[mf][2], ah[mf][3], uA16 + off);
                }
                uint32_t bh[8][2];
                #pragma unroll
                for (int p = 0; p < 4; p++) {
                    uint32_t off = (uint32_t)((wn * 64 + p * 16 + b_lrow) * 80 + (kc + b_c8) * 2);
                    uint32_t r0, r1, r2, r3;
                    ldmatrix_x4(r0, r1, r2, r3, uB + off);
                    bh[2*p][0] = r0; bh[2*p][1] = r1; bh[2*p+1][0] = r2; bh[2*p+1][1] = r3;
                }
                #pragma unroll
                for (int mf = 0; mf < 2; mf++)
                    #pragma unroll
                    for (int nf = 0; nf < 8; nf++)
                        mma_f16(acc[mf][nf], ah[mf], bh[nf]);
            }
            __syncthreads();   // A16 / stage reuse safe
        }

        // ---- epilogue: store C, fused alpha from fp32 acc ----
        const int crow = lane >> 2;
        const int ccol = (lane & 3) << 1;
        float aS[2][2][2], aD[2][2][2];
        #pragma unroll
        for (int i = 0; i < 2; i++)
            #pragma unroll
            for (int j = 0; j < 2; j++)
                { aS[i][j][0]=aS[i][j][1]=aD[i][j][0]=aD[i][j][1]=0.f; }

        #pragma unroll
        for (int mf = 0; mf < 2; mf++) {
            int rbase = row0 + wm * 32 + mf * 16 + crow;
            #pragma unroll
            for (int nf = 0; nf < 8; nf++) {
                int col = wn * 64 + nf * 8 + ccol;
                int hl = nf >> 2;
                #pragma unroll
                for (int half = 0; half < 2; half++) {
                    int r = rbase + half * 8;
                    float v0 = acc[mf][nf][half * 2 + 0];
                    float v1 = acc[mf][nf][half * 2 + 1];
                    if (asrc) {
                        aS[mf][half][hl] += v0 * asrc[col] + v1 * asrc[col + 1];
                        aD[mf][half][hl] += v0 * adst[col] + v1 * adst[col + 1];
                    }
                    if (r >= M) continue;
                    if (bias) { v0 += bias[col]; v1 += bias[col + 1]; }
                    if (apply_gelu) {
                        v0 = 0.5f * v0 * (1.0f + erff(v0 * 0.70710678118654752f));
                        v1 = 0.5f * v1 * (1.0f + erff(v1 * 0.70710678118654752f));
                    }
                    float2 o; o.x = v0; o.y = v1;
                    *(float2*)&C[(size_t)r * HID + col] = o;
                }
            }
        }

        if (asrc) {
            #pragma unroll
            for (int mf = 0; mf < 2; mf++)
                #pragma unroll
                for (int half = 0; half < 2; half++)
                    #pragma unroll
                    for (int hl = 0; hl < 2; hl++) {
                        float s = aS[mf][half][hl], d = aD[mf][half][hl];
                        s += __shfl_xor_sync(0xffffffffu, s, 1);
                        s += __shfl_xor_sync(0xffffffffu, s, 2);
                        d += __shfl_xor_sync(0xffffffffu, d, 1);
                        d += __shfl_xor_sync(0xffffffffu, d, 2);
                        aS[mf][half][hl] = s; aD[mf][half][hl] = d;
                    }
            if ((lane & 3) == 0) {
                #pragma unroll
                for (int mf = 0; mf < 2; mf++)
                    #pragma unroll
                    for (int half = 0; half < 2; half++) {
                        int r = row0 + wm * 32 + mf * 16 + crow + half * 8;
                        if (r < M) {
                            int hbase = r * HEADS + wn * 2;
                            g_as[hbase + 0] = aS[mf][half][0];
                            g_as[hbase + 1] = aS[mf][half][1];
                            g_ad[hbase + 0] = aD[mf][half][0];
                            g_ad[hbase + 1] = aD[mf][half][1];
                        }
                    }
            }
        }
        __syncthreads();
    }

    // ---- post-loop CSR scatter (GEMM1 only) ----
    if (ei_scat) {
        int tid0 = blockIdx.x * 256 + t;
        int stride = (int)gridDim.x * 256;
        for (int e = tid0; e < EE; e += stride) {
            int src = ei_scat[e];
            int dst = ei_scat[EE + e];
            g_colsrc[atomicAdd(&g_cursor[dst], 1)] = src;
        }
    }
}

// ================= warp-per-node GAT aggregation: direct-exp softmax =================
__global__ __launch_bounds__(256)
void gat_agg_kernel(const float* __restrict__ bias, float* __restrict__ Xout) {
    int gtid = blockIdx.x * blockDim.x + threadIdx.x;
    int node = gtid >> 5;
    if (node >= NN) return;
    int lane = threadIdx.x & 31;
    int head = lane >> 3;

    const float4* H4 = (const float4*)g_H;
    float ad = g_ad[node * HEADS + head];

    float e0 = g_as[node * HEADS + head] + ad;
    e0 = fmaxf(e0, 0.2f * e0);
    float w0 = __expf(e0);
    float dsum = w0;
    float4 hs = H4[node * 32 + lane];
    float4 acc;
    acc.x = w0 * hs.x; acc.y = w0 * hs.y; acc.z = w0 * hs.z; acc.w = w0 * hs.w;

    int beg = g_rowptr[node];
    int end = g_rowptr[node + 1];
    int i = beg;

    if ((i & 1) && i < end) {
        int src = g_colsrc[i];
        float e = g_as[src * HEADS + head] + ad;
        e = fmaxf(e, 0.2f * e);
        float w = __expf(e);
        float4 hv = H4[src * 32 + lane];
        dsum += w;
        acc.x = fmaf(w, hv.x, acc.x);
        acc.y = fmaf(w, hv.y, acc.y);
        acc.z = fmaf(w, hv.z, acc.z);
        acc.w = fmaf(w, hv.w, acc.w);
        i++;
    }

    for (; i + 1 < end; i += 2) {
        int2 s2 = *(const int2*)&g_colsrc[i];
        float e1 = g_as[s2.x * HEADS + head] + ad;
        float e2 = g_as[s2.y * HEADS + head] + ad;
        float4 h1 = H4[s2.x * 32 + lane];
        float4 h2 = H4[s2.y * 32 + lane];
        e1 = fmaxf(e1, 0.2f * e1);
        e2 = fmaxf(e2, 0.2f * e2);
        float w1 = __expf(e1);
        float w2 = __expf(e2);
        dsum += w1 + w2;
        acc.x = fmaf(w1, h1.x, fmaf(w2, h2.x, acc.x));
        acc.y = fmaf(w1, h1.y, fmaf(w2, h2.y, acc.y));
        acc.z = fmaf(w1, h1.z, fmaf(w2, h2.z, acc.z));
        acc.w = fmaf(w1, h1.w, fmaf(w2, h2.w, acc.w));
    }

    if (i < end) {
        int src = g_colsrc[i];
        float e = g_as[src * HEADS + head] + ad;
        e = fmaxf(e, 0.2f * e);
        float w = __expf(e);
        float4 hv = H4[src * 32 + lane];
        dsum += w;
        acc.x = fmaf(w, hv.x, acc.x);
        acc.y = fmaf(w, hv.y, acc.y);
        acc.z = fmaf(w, hv.z, acc.z);
        acc.w = fmaf(w, hv.w, acc.w);
    }

    float inv = 1.0f / dsum;
    float4 bv = ((const float4*)bias)[lane];
    float4 o;
    o.x = fmaxf(fmaf(acc.x, inv, bv.x), 0.0f);
    o.y = fmaxf(fmaf(acc.y, inv, bv.y), 0.0f);
    o.z = fmaxf(fmaf(acc.z, inv, bv.z), 0.0f);
    o.w = fmaxf(fmaf(acc.w, inv, bv.w), 0.0f);
    ((float4*)Xout)[node * 32 + lane] = o;
}

// ================= pool (+ cursor re-zero for next replay) =================
#define POOL_GRID (GG + 782)
__global__ __launch_bounds__(128)
void pool2_kernel(float* __restrict__ out) {
    int b = blockIdx.x, t = threadIdx.x;
    if (b >= GG) {
        int i = (b - GG) * 128 + t;
        if (i < NN) g_cursor[i] = 0;
        return;
    }
    int beg = g_gstart[b], end = g_gstart[b + 1];
    float s = 0.0f;
    for (int r = beg; r < end; r++) s += g_X[(size_t)r * HID + t];
    out[b * HID + t] = s;
}

// ================= launch =================
extern "C" void kernel_launch(void* const* d_in, const int* in_sizes, int n_in,
                              void* d_out, int out_size) {
    const float* nf    = (const float*)d_in[0];
    const int*   ei    = (const int*)d_in[1];
    const int*   batch = (const int*)d_in[2];
    const float* W1    = (const float*)d_in[3];
    const float* b1    = (const float*)d_in[4];
    const float* Wg    = (const float*)d_in[5];
    const float* a_src = (const float*)d_in[6];
    const float* a_dst = (const float*)d_in[7];
    const float* bg    = (const float*)d_in[8];
    float* out = (float*)d_out;

    float *pX, *pH;
    cudaGetSymbolAddress((void**)&pX, g_X);
    cudaGetSymbolAddress((void**)&pH, g_H);
    __half *pW1T, *pWgT;
    cudaGetSymbolAddress((void**)&pW1T, g_W1T);
    cudaGetSymbolAddress((void**)&pWgT, g_WgT);

    cudaFuncSetAttribute(mma_gemm_kernel,
                         cudaFuncAttributeMaxDynamicSharedMemorySize, TCG_SMEM);

    // ---- fused init: hist + weight prep + gstart ----
    init_kernel<<<INIT_GRID, 256>>>(W1, Wg, ei, batch);

    // ---- 2-launch scan ----
    const int nsb = (NN + 1023) / 1024;     // 98
    scan_block_kernel<<<nsb, 1024>>>();
    scan_add2_kernel<<<nsb, 1024>>>(nsb);

    // ---- X = gelu(nf @ W1 + b1), persistent + post-loop scatter ----
    mma_gemm_kernel<<<GEMM_BLOCKS, 256, TCG_SMEM>>>(
        nf, pW1T, b1, pX, NN, INDIM, 1,
        nullptr, nullptr, ei);

    // ---- GAT layers (alpha fused into GEMM epilogue) ----
    for (int l = 0; l < 2; l++) {
        mma_gemm_kernel<<<GEMM_BLOCKS, 256, TCG_SMEM>>>(
            pX, pWgT + (size_t)l * HID * HID, nullptr, pH, NN, HID, 0,
            a_src + l * HEADS * 32, a_dst + l * HEADS * 32,
            nullptr);
        gat_agg_kernel<<<(NN * 32 + 255) / 256, 256>>>(bg + l * HID, pX);
    }

    // ---- pool + cursor re-zero ----
    pool2_kernel<<<POOL_GRID, 128>>>(out);
}